// round 8
// baseline (speedup 1.0000x reference)
#include <cuda_runtime.h>
#include <cuda_fp16.h>
#include <cstdint>

// ---------------------------------------------------------------------------
// Problem constants
// ---------------------------------------------------------------------------
#define OUT_N    8192
#define IN_K     8192
#define BATCH    64
#define TILE_N   128                  // W rows per CTA
#define KSPLIT   16
#define NGRPS    (OUT_N / TILE_N)     // 64
#define CHPC     (64 / KSPLIT)        // 4 scale-chunks (k128) per CTA
#define NSUB     (CHPC * 2)           // 8 k64 subchunks per CTA
#define NTHREADS 256

// W stage: 128 rows x 64 halfs, padded row stride 144B (odd multiple of 16B)
#define RS       144
#define WSTAGE   (TILE_N * RS)        // 18432 B

// ---------------------------------------------------------------------------
// Static scratch (allowed: no runtime allocation)
// ---------------------------------------------------------------------------
// x in mma-A-fragment order: [ktile 512][mtile 4][lane 32] x 16B
__device__ __align__(16) __half g_xfrag[(IN_K / 16) * 4 * 32 * 8];   // 1 MiB
// split-K partials: [KSPLIT][BATCH][OUT_N] fp32
__device__ float g_part[KSPLIT * BATCH * OUT_N];                     // 32 MiB

// ---------------------------------------------------------------------------
// PTX helpers (family-portable: ptxas target is sm_103, no tcgen05)
// ---------------------------------------------------------------------------
__device__ __forceinline__ void ldsm_x4(uint32_t& r0, uint32_t& r1, uint32_t& r2,
                                        uint32_t& r3, uint32_t addr) {
    asm volatile("ldmatrix.sync.aligned.m8n8.x4.shared.b16 {%0,%1,%2,%3}, [%4];"
                 : "=r"(r0), "=r"(r1), "=r"(r2), "=r"(r3) : "r"(addr));
}
__device__ __forceinline__ void mma_16816(float* c, uint32_t a0, uint32_t a1,
                                          uint32_t a2, uint32_t a3,
                                          uint32_t b0, uint32_t b1) {
    asm volatile(
        "mma.sync.aligned.m16n8k16.row.col.f32.f16.f16.f32 "
        "{%0,%1,%2,%3},{%4,%5,%6,%7},{%8,%9},{%0,%1,%2,%3};"
        : "+f"(c[0]), "+f"(c[1]), "+f"(c[2]), "+f"(c[3])
        : "r"(a0), "r"(a1), "r"(a2), "r"(a3), "r"(b0), "r"(b1));
}

// ---------------------------------------------------------------------------
// Kernel 1: repack x (fp32) into mma A-fragment order (fp16)
//   fragment (ktg, mtg): thread lane holds
//   a0=(r,c)(r,c+1) a1=(r+8,c)(r+8,c+1) a2=(r,c+8)(r,c+9) a3=(r+8,c+8)(r+8,c+9)
//   with r = mtg*16 + lane/4, c = ktg*16 + (lane%4)*2
// ---------------------------------------------------------------------------
__global__ __launch_bounds__(256) void prep_kernel(const float* __restrict__ x) {
    int i = blockIdx.x * 256 + threadIdx.x;          // 0..65535
    int lane = i & 31;
    int mtg  = (i >> 5) & 3;
    int ktg  = i >> 7;                               // 0..511
    int r = mtg * 16 + (lane >> 2);
    int c = ktg * 16 + (lane & 3) * 2;
    const float* xr = x + (size_t)r * IN_K + c;
    float2 v0 = *reinterpret_cast<const float2*>(xr);
    float2 v1 = *reinterpret_cast<const float2*>(xr + 8 * IN_K);
    float2 v2 = *reinterpret_cast<const float2*>(xr + 8);
    float2 v3 = *reinterpret_cast<const float2*>(xr + 8 * IN_K + 8);
    __half2 h0 = __floats2half2_rn(v0.x, v0.y);
    __half2 h1 = __floats2half2_rn(v1.x, v1.y);
    __half2 h2 = __floats2half2_rn(v2.x, v2.y);
    __half2 h3 = __floats2half2_rn(v3.x, v3.y);
    uint4 o;
    o.x = *reinterpret_cast<uint32_t*>(&h0);
    o.y = *reinterpret_cast<uint32_t*>(&h1);
    o.z = *reinterpret_cast<uint32_t*>(&h2);
    o.w = *reinterpret_cast<uint32_t*>(&h3);
    reinterpret_cast<uint4*>(g_xfrag)[i] = o;
}

// ---------------------------------------------------------------------------
// Kernel 2: int4-dequant GEMM (mma.sync), W-only SMEM double buffer.
// Grid = 1024 CTAs: bid & 63 = n-group (128 W rows), bid >> 6 = k-group.
// Each CTA: 8 k64 subchunks. Warp layout 2(m) x 4(n): 32 rows x 32 cols.
// A operand straight from g_xfrag (LDG.128), B via dequant->STS->ldmatrix.
// Epilogue: plain STG.64 into g_part[k-group] (no atomics).
// ---------------------------------------------------------------------------
__global__ __launch_bounds__(NTHREADS, 3)
void dq_gemm_kernel(const int*   __restrict__ packed,
                    const float* __restrict__ scales)
{
    __shared__ __align__(16) char sW[2 * WSTAGE];
    __shared__ float sScale[CHPC * TILE_N];

    const uint32_t sb = (uint32_t)__cvta_generic_to_shared(sW);
    const int tid  = threadIdx.x;
    const int wid  = tid >> 5;
    const int lane = tid & 31;
    const int mh   = wid & 1;            // batch half (m 0..31 / 32..63)
    const int ng   = wid >> 1;           // 32-col group
    const int n0   = (blockIdx.x & 63) * TILE_N;
    const int kg   = blockIdx.x >> 6;    // 0..15
    const int ks0  = kg * NSUB;          // global k64-subchunk base

    float acc[2][4][4];
    #pragma unroll
    for (int m = 0; m < 2; m++)
        #pragma unroll
        for (int n = 0; n < 4; n++)
            #pragma unroll
            for (int j = 0; j < 4; j++) acc[m][n][j] = 0.f;

    const uint4* pk4 = reinterpret_cast<const uint4*>(packed); // row = 1024 uint4
    const uint4* xf4 = reinterpret_cast<const uint4*>(g_xfrag);
    const uint32_t c1032b = 0x64086408u;                       // half2(1032,1032)
    const __half2 c1032 = *reinterpret_cast<const __half2*>(&c1032b);

    // stage scale table once: [CHPC][TILE_N]
    #pragma unroll
    for (int i = 0; i < (CHPC * TILE_N) / NTHREADS; i++) {
        int idx = tid + i * NTHREADS;
        int ch = idx >> 7, row = idx & 127;
        sScale[idx] = scales[(size_t)(n0 + row) * 64 + kg * CHPC + ch];
    }

    // packed-W prefetch: one k64 sub = 1024 uint4 = 4 per thread
    uint4 pv[4];
    auto prefetch = [&](int ks) {
        #pragma unroll
        for (int j = 0; j < 4; j++) {
            int u = tid + (j << 8);              // 0..1023
            int row = u >> 3, kv = u & 7;
            pv[j] = pk4[(size_t)(n0 + row) * 1024 + ks * 8 + kv];
        }
    };
    prefetch(ks0);

    for (int sub = 0; sub < NSUB; sub++) {
        const int s = sub & 1;
        const uint32_t stage = sb + s * WSTAGE;
        const int ktbase = (ks0 + sub) * 4;      // global k16-tile base

        __syncthreads();                         // stage s free

        // early A-frag issue for ktl=0 (independent of SMEM)
        uint4 a_cur[2];
        #pragma unroll
        for (int mt = 0; mt < 2; mt++)
            a_cur[mt] = xf4[(size_t)(ktbase * 4 + (mh * 2 + mt)) * 32 + lane];

        // dequant pv -> W stage (4 x STS.128 per thread)
        const int chs = sub >> 1;
        #pragma unroll
        for (int j = 0; j < 4; j++) {
            int u = tid + (j << 8);
            int row = u >> 3, kv = u & 7;
            __half2 s2 = __float2half2_rn(sScale[(chs << 7) + row]);
            uint32_t w[4] = { pv[j].x, pv[j].y, pv[j].z, pv[j].w };
            uint32_t o[4];
            #pragma unroll
            for (int q = 0; q < 4; q++) {
                uint32_t t = ((w[q] * 0x1001u) & 0x000F000Fu) | 0x64006400u;
                __half2 hv = __hmul2(__hsub2(*reinterpret_cast<__half2*>(&t), c1032), s2);
                o[q] = *reinterpret_cast<uint32_t*>(&hv);
            }
            asm volatile("st.shared.v4.b32 [%0], {%1,%2,%3,%4};"
                         :: "r"(stage + row * RS + kv * 16),
                            "r"(o[0]), "r"(o[1]), "r"(o[2]), "r"(o[3]) : "memory");
        }

        if (sub + 1 < NSUB) prefetch(ks0 + sub + 1);   // overlaps MMA below

        __syncthreads();                         // W[s] visible

        // MMA: 4 k16 tiles, warp tile 32(m) x 32(n)
        #pragma unroll
        for (int ktl = 0; ktl < 4; ktl++) {
            uint4 a_nxt[2];
            if (ktl < 3) {
                #pragma unroll
                for (int mt = 0; mt < 2; mt++)
                    a_nxt[mt] = xf4[(size_t)((ktbase + ktl + 1) * 4 + (mh * 2 + mt)) * 32 + lane];
            }
            uint32_t b[4][2];
            #pragma unroll
            for (int np = 0; np < 2; np++) {
                int br = ng * 32 + np * 16 + ((lane >> 4) & 1) * 8 + (lane & 7);
                int bc = ktl * 16 + ((lane >> 3) & 1) * 8;
                ldsm_x4(b[np*2][0], b[np*2][1], b[np*2+1][0], b[np*2+1][1],
                        stage + (uint32_t)(br * RS + bc * 2));
            }
            #pragma unroll
            for (int mt = 0; mt < 2; mt++) {
                #pragma unroll
                for (int nt = 0; nt < 4; nt++)
                    mma_16816(acc[mt][nt], a_cur[mt].x, a_cur[mt].y,
                              a_cur[mt].z, a_cur[mt].w, b[nt][0], b[nt][1]);
            }
            a_cur[0] = a_nxt[0];
            a_cur[1] = a_nxt[1];
        }
    }

    // epilogue: plain STG.64 into this k-group's partial plane
    float* base = g_part + (size_t)kg * BATCH * OUT_N;
    #pragma unroll
    for (int mt = 0; mt < 2; mt++) {
        #pragma unroll
        for (int nt = 0; nt < 4; nt++) {
            int m = mh * 32 + mt * 16 + (lane >> 2);
            int n = n0 + ng * 32 + nt * 8 + (lane & 3) * 2;
            *reinterpret_cast<float2*>(base + (size_t)m * OUT_N + n) =
                make_float2(acc[mt][nt][0], acc[mt][nt][1]);
            *reinterpret_cast<float2*>(base + (size_t)(m + 8) * OUT_N + n) =
                make_float2(acc[mt][nt][2], acc[mt][nt][3]);
        }
    }
}

// ---------------------------------------------------------------------------
// Kernel 3: split-K reduction (16-way, float4, L2-resident)
// ---------------------------------------------------------------------------
__global__ __launch_bounds__(256) void reduce_kernel(float* __restrict__ out) {
    const int i = blockIdx.x * 256 + threadIdx.x;        // 0..131071 float4
    const float4* gp = reinterpret_cast<const float4*>(g_part);
    const int stride = BATCH * OUT_N / 4;                // 131072
    float4 s = gp[i];
    #pragma unroll
    for (int kg = 1; kg < KSPLIT; kg++) {
        float4 v = gp[(size_t)kg * stride + i];
        s.x += v.x; s.y += v.y; s.z += v.z; s.w += v.w;
    }
    reinterpret_cast<float4*>(out)[i] = s;
}

// ---------------------------------------------------------------------------
extern "C" void kernel_launch(void* const* d_in, const int* in_sizes, int n_in,
                              void* d_out, int out_size) {
    const float* x      = (const float*)d_in[0];
    const int*   packed = (const int*)d_in[1];
    const float* scales = (const float*)d_in[2];
    float*       out    = (float*)d_out;

    static bool configured = false;
    if (!configured) {
        cudaFuncSetAttribute(dq_gemm_kernel,
                             cudaFuncAttributePreferredSharedMemoryCarveout,
                             cudaSharedmemCarveoutMaxShared);
        configured = true;
    }

    prep_kernel<<<256, 256>>>(x);
    dq_gemm_kernel<<<NGRPS * KSPLIT, NTHREADS>>>(packed, scales);
    reduce_kernel<<<512, 256>>>(out);
}

// round 9
// speedup vs baseline: 1.3584x; 1.3584x over previous
#include <cuda_runtime.h>
#include <cuda_fp16.h>
#include <cstdint>

// ---------------------------------------------------------------------------
// Problem constants
// ---------------------------------------------------------------------------
#define OUT_N    8192
#define IN_K     8192
#define BATCH    64
#define GROUP    128                  // k per chunk (= scale group)
#define TILE_N   128                  // W rows per CTA
#define KSPLIT   8
#define NGRPS    (OUT_N / TILE_N)     // 64
#define CHPC     (64 / KSPLIT)        // 8 chunks per CTA
#define NTHREADS 256

// SMEM layout (bytes). Padded row stride: 136 halfs = 272 B (16B-mult, odd x16)
#define RSTRIDE     272
#define W_BYTES     (TILE_N * RSTRIDE)     // 34816
#define X_OFF       W_BYTES
#define X_BYTES     (BATCH * RSTRIDE)      // 17408
#define STAGE_BYTES (W_BYTES + X_BYTES)    // 52224
#define SCALE_OFF   (2 * STAGE_BYTES)      // 104448
#define SCALE_BYTES (CHPC * TILE_N * 4)    // 4096
#define SMEM_TOTAL  (SCALE_OFF + SCALE_BYTES)  // 108544 -> 2 CTAs/SM

// Static scratch: x converted to fp16 (1 MiB)
__device__ __half g_xh[BATCH * IN_K];

// ---------------------------------------------------------------------------
// PTX helpers (family-portable: ptxas target is sm_103, no tcgen05)
// ---------------------------------------------------------------------------
__device__ __forceinline__ void ldsm_x4(uint32_t& r0, uint32_t& r1, uint32_t& r2,
                                        uint32_t& r3, uint32_t addr) {
    asm volatile("ldmatrix.sync.aligned.m8n8.x4.shared.b16 {%0,%1,%2,%3}, [%4];"
                 : "=r"(r0), "=r"(r1), "=r"(r2), "=r"(r3) : "r"(addr));
}
__device__ __forceinline__ void mma_16816(float* c, uint32_t a0, uint32_t a1,
                                          uint32_t a2, uint32_t a3,
                                          uint32_t b0, uint32_t b1) {
    asm volatile(
        "mma.sync.aligned.m16n8k16.row.col.f32.f16.f16.f32 "
        "{%0,%1,%2,%3},{%4,%5,%6,%7},{%8,%9},{%0,%1,%2,%3};"
        : "+f"(c[0]), "+f"(c[1]), "+f"(c[2]), "+f"(c[3])
        : "r"(a0), "r"(a1), "r"(a2), "r"(a3), "r"(b0), "r"(b1));
}
__device__ __forceinline__ void cp_async16(uint32_t dst, const void* src) {
    asm volatile("cp.async.cg.shared.global [%0], [%1], 16;"
                 :: "r"(dst), "l"(src) : "memory");
}
__device__ __forceinline__ void cp_commit() {
    asm volatile("cp.async.commit_group;" ::: "memory");
}

// ---------------------------------------------------------------------------
// Kernel 1: convert x fp32->fp16 AND zero-init out (both 131072 float4 units)
// ---------------------------------------------------------------------------
__global__ __launch_bounds__(256) void prep_kernel(const float* __restrict__ x,
                                                   float* __restrict__ out) {
    int i = blockIdx.x * 256 + threadIdx.x;
    float4 v = reinterpret_cast<const float4*>(x)[i];
    __half2 h01 = __floats2half2_rn(v.x, v.y);
    __half2 h23 = __floats2half2_rn(v.z, v.w);
    uint2 o;
    o.x = *reinterpret_cast<uint32_t*>(&h01);
    o.y = *reinterpret_cast<uint32_t*>(&h23);
    reinterpret_cast<uint2*>(g_xh)[i] = o;
    reinterpret_cast<float4*>(out)[i] = make_float4(0.f, 0.f, 0.f, 0.f);
}

// ---------------------------------------------------------------------------
// Kernel 2: int4-dequant GEMM (mma.sync), double-buffered, ONE barrier/chunk.
// Grid = 512 CTAs: bid & 63 = n-group (128 W rows), bid >> 6 = k-group (8 ch).
// Warp layout 2(m) x 4(n): warp owns 32 batch rows x 32 output cols.
// Phase shift: iteration ch stages chunk ch+1 (STS W, cp.async x) BEFORE
// running MMA(ch) on the other buffer -> ldsm never waits on same-interval STS.
// ---------------------------------------------------------------------------
__global__ __launch_bounds__(NTHREADS, 2)
void dq_gemm_kernel(const int*   __restrict__ packed,
                    const float* __restrict__ scales,
                    float*       __restrict__ out)
{
    extern __shared__ __align__(16) char dsm[];
    const uint32_t sb = (uint32_t)__cvta_generic_to_shared(dsm);
    float* sScale = reinterpret_cast<float*>(dsm + SCALE_OFF);

    const int tid  = threadIdx.x;
    const int wid  = tid >> 5;
    const int lane = tid & 31;
    const int mh   = wid & 1;          // batch half
    const int ng   = wid >> 1;         // 32-col group
    const int n0   = (blockIdx.x & 63) * TILE_N;
    const int kc0  = (blockIdx.x >> 6) * CHPC;

    float acc[2][4][4];
    #pragma unroll
    for (int m = 0; m < 2; m++)
        #pragma unroll
        for (int n = 0; n < 4; n++)
            #pragma unroll
            for (int j = 0; j < 4; j++) acc[m][n][j] = 0.f;

    const uint4* pk4 = reinterpret_cast<const uint4*>(packed); // row stride 1024
    const uint32_t c1032b = 0x64086408u;                       // half2(1032,1032)
    const __half2 c1032 = *reinterpret_cast<const __half2*>(&c1032b);

    // ---- stage the scale table once: [CHPC][TILE_N] -----------------------
    #pragma unroll
    for (int i = 0; i < (CHPC * TILE_N) / NTHREADS; i++) {
        int idx = tid + i * NTHREADS;                // 0..1023
        int ch = idx >> 7, row = idx & 127;
        sScale[idx] = scales[(size_t)(n0 + row) * 64 + kc0 + ch];
    }

    // ---- packed-W register prefetch (one chunk = 2048 uint4 = 8/thread) ---
    uint4 pv[8];
    auto prefetch = [&](int kc) {
        #pragma unroll
        for (int i = 0; i < 8; i++) {
            int u = tid + (i << 8);                  // 0..2047
            int row = u >> 4, kv = u & 15;
            pv[i] = pk4[(size_t)(n0 + row) * 1024 + kc * 16 + kv];
        }
    };

    // ---- x tile cp.async (1024 x 16B units = 4/thread) --------------------
    auto stage_x = [&](int kc, int s) {
        const uint32_t xb = sb + s * STAGE_BYTES + X_OFF;
        #pragma unroll
        for (int j = 0; j < 4; j++) {
            int u = tid + (j << 8);                  // 0..1023
            int b = u >> 4, kv = u & 15;
            cp_async16(xb + b * RSTRIDE + kv * 16,
                       &g_xh[(size_t)b * IN_K + kc * GROUP + kv * 8]);
        }
        cp_commit();
    };

    // dequant pv (chunk local index lch) -> W buffer s (8 x STS.128/thread)
    auto dequant_sts = [&](int s, int lch) {
        const uint32_t stage = sb + s * STAGE_BYTES;
        #pragma unroll
        for (int i = 0; i < 8; i++) {
            int u = tid + (i << 8);
            int row = u >> 4, kv = u & 15;
            __half2 s2 = __float2half2_rn(sScale[(lch << 7) + row]);
            uint32_t w[4] = { pv[i].x, pv[i].y, pv[i].z, pv[i].w };
            uint32_t o[4];
            #pragma unroll
            for (int j = 0; j < 4; j++) {
                uint32_t t = ((w[j] * 0x1001u) & 0x000F000Fu) | 0x64006400u;
                __half2 hv = __hmul2(__hsub2(*reinterpret_cast<__half2*>(&t), c1032), s2);
                o[j] = *reinterpret_cast<uint32_t*>(&hv);
            }
            asm volatile("st.shared.v4.b32 [%0], {%1,%2,%3,%4};"
                         :: "r"(stage + row * RSTRIDE + kv * 16),
                            "r"(o[0]), "r"(o[1]), "r"(o[2]), "r"(o[3]) : "memory");
        }
    };

    // ---- prologue ---------------------------------------------------------
    prefetch(kc0);           // pv = packed[chunk 0]
    stage_x(kc0, 0);         // x[0] in flight (group pending)
    __syncthreads();         // sScale visible to all
    dequant_sts(0, 0);       // W[0] -> stage 0 (STS issued)
    prefetch(kc0 + 1);       // pv = packed[chunk 1]

    // Loop invariant at iteration entry (chunk ch, s = ch&1):
    //   x[ch] cp.async group pending; W[ch] STS issued into stage s;
    //   pv = packed[ch+1].
    for (int ch = 0; ch < CHPC; ch++) {
        const int s = ch & 1;

        asm volatile("cp.async.wait_group 0;" ::: "memory");  // x[ch] landed
        __syncthreads();     // W[ch]/x[ch] visible; stage s^1 free of readers

        if (ch + 1 < CHPC) {
            stage_x(kc0 + ch + 1, s ^ 1);     // x[ch+1] in flight
            dequant_sts(s ^ 1, ch + 1);       // W[ch+1] STS (other buffer)
            if (ch + 2 < CHPC) prefetch(kc0 + ch + 2);  // LDGs overlap MMA
        }

        // ---- MMA(ch): 8 k16 tiles, warp tile 32(m) x 32(n), stage s -------
        const uint32_t wbase = sb + s * STAGE_BYTES;
        const uint32_t xbase = wbase + X_OFF;
        #pragma unroll
        for (int kt = 0; kt < 8; kt++) {
            uint32_t b[4][2];             // [nt][b0,b1]
            #pragma unroll
            for (int np = 0; np < 2; np++) {
                int br = ng * 32 + np * 16 + ((lane >> 4) & 1) * 8 + (lane & 7);
                int bc = kt * 16 + ((lane >> 3) & 1) * 8;
                ldsm_x4(b[np*2][0], b[np*2][1], b[np*2+1][0], b[np*2+1][1],
                        wbase + (uint32_t)(br * RSTRIDE + bc * 2));
            }
            #pragma unroll
            for (int mt = 0; mt < 2; mt++) {
                uint32_t a0, a1, a2, a3;
                int ar = mh * 32 + mt * 16 + (lane & 15);
                int ac = kt * 16 + (lane >> 4) * 8;
                ldsm_x4(a0, a1, a2, a3, xbase + (uint32_t)(ar * RSTRIDE + ac * 2));
                #pragma unroll
                for (int nt = 0; nt < 4; nt++)
                    mma_16816(acc[mt][nt], a0, a1, a2, a3, b[nt][0], b[nt][1]);
            }
        }
    }

    // ---- epilogue: vectorized float2 atomics (k-split merge) --------------
    #pragma unroll
    for (int mt = 0; mt < 2; mt++) {
        #pragma unroll
        for (int nt = 0; nt < 4; nt++) {
            int m = mh * 32 + mt * 16 + (lane >> 2);
            int n = n0 + ng * 32 + nt * 8 + (lane & 3) * 2;
            atomicAdd(reinterpret_cast<float2*>(&out[(size_t)m * OUT_N + n]),
                      make_float2(acc[mt][nt][0], acc[mt][nt][1]));
            atomicAdd(reinterpret_cast<float2*>(&out[(size_t)(m + 8) * OUT_N + n]),
                      make_float2(acc[mt][nt][2], acc[mt][nt][3]));
        }
    }
}

// ---------------------------------------------------------------------------
extern "C" void kernel_launch(void* const* d_in, const int* in_sizes, int n_in,
                              void* d_out, int out_size) {
    const float* x      = (const float*)d_in[0];
    const int*   packed = (const int*)d_in[1];
    const float* scales = (const float*)d_in[2];
    float*       out    = (float*)d_out;

    cudaFuncSetAttribute(dq_gemm_kernel,
                         cudaFuncAttributeMaxDynamicSharedMemorySize, SMEM_TOTAL);

    prep_kernel<<<512, 256>>>(x, out);
    dq_gemm_kernel<<<NGRPS * KSPLIT, NTHREADS, SMEM_TOTAL>>>(packed, scales, out);
}

// round 10
// speedup vs baseline: 1.5132x; 1.1140x over previous
#include <cuda_runtime.h>
#include <cuda_fp16.h>
#include <cstdint>

// ---------------------------------------------------------------------------
// Problem constants
// ---------------------------------------------------------------------------
#define OUT_N    8192
#define IN_K     8192
#define BATCH    64
#define TILE_N   128                  // W rows per CTA
#define KSPLIT   8
#define NGRPS    (OUT_N / TILE_N)     // 64
#define NSUB     16                   // k64 subchunks per CTA (k total 1024)
#define NCH      8                    // k128 scale-chunks per CTA
#define NTHREADS 256

// SMEM layout (bytes). Rows hold 64 halfs = 128 B, padded stride 144 B
// (odd multiple of 16 B -> conflict-free ldmatrix over 8-row groups)
#define RS          144
#define W_BYTES     (TILE_N * RS)          // 18432
#define X_OFF       W_BYTES
#define X_BYTES     (BATCH * RS)           // 9216
#define STAGE_BYTES (W_BYTES + X_BYTES)    // 27648
#define SCALE_OFF   (2 * STAGE_BYTES)      // 55296
#define SCALE_BYTES (NCH * TILE_N * 4)     // 4096
#define SMEM_TOTAL  (SCALE_OFF + SCALE_BYTES)  // 59392 -> 3 CTAs/SM

// Static scratch: x converted to fp16 (1 MiB)
__device__ __half g_xh[BATCH * IN_K];

// ---------------------------------------------------------------------------
// PTX helpers (family-portable: ptxas target is sm_103, no tcgen05)
// ---------------------------------------------------------------------------
__device__ __forceinline__ void ldsm_x4(uint32_t& r0, uint32_t& r1, uint32_t& r2,
                                        uint32_t& r3, uint32_t addr) {
    asm volatile("ldmatrix.sync.aligned.m8n8.x4.shared.b16 {%0,%1,%2,%3}, [%4];"
                 : "=r"(r0), "=r"(r1), "=r"(r2), "=r"(r3) : "r"(addr));
}
__device__ __forceinline__ void mma_16816(float* c, uint32_t a0, uint32_t a1,
                                          uint32_t a2, uint32_t a3,
                                          uint32_t b0, uint32_t b1) {
    asm volatile(
        "mma.sync.aligned.m16n8k16.row.col.f32.f16.f16.f32 "
        "{%0,%1,%2,%3},{%4,%5,%6,%7},{%8,%9},{%0,%1,%2,%3};"
        : "+f"(c[0]), "+f"(c[1]), "+f"(c[2]), "+f"(c[3])
        : "r"(a0), "r"(a1), "r"(a2), "r"(a3), "r"(b0), "r"(b1));
}
__device__ __forceinline__ void cp_async16(uint32_t dst, const void* src) {
    asm volatile("cp.async.cg.shared.global [%0], [%1], 16;"
                 :: "r"(dst), "l"(src) : "memory");
}
__device__ __forceinline__ void cp_commit() {
    asm volatile("cp.async.commit_group;" ::: "memory");
}

// ---------------------------------------------------------------------------
// Kernel 1: convert x fp32->fp16 AND zero-init out (both 131072 float4 units)
// ---------------------------------------------------------------------------
__global__ __launch_bounds__(256) void prep_kernel(const float* __restrict__ x,
                                                   float* __restrict__ out) {
    int i = blockIdx.x * 256 + threadIdx.x;
    float4 v = reinterpret_cast<const float4*>(x)[i];
    __half2 h01 = __floats2half2_rn(v.x, v.y);
    __half2 h23 = __floats2half2_rn(v.z, v.w);
    uint2 o;
    o.x = *reinterpret_cast<uint32_t*>(&h01);
    o.y = *reinterpret_cast<uint32_t*>(&h23);
    reinterpret_cast<uint2*>(g_xh)[i] = o;
    reinterpret_cast<float4*>(out)[i] = make_float4(0.f, 0.f, 0.f, 0.f);
}

// ---------------------------------------------------------------------------
// Kernel 2: int4-dequant GEMM (mma.sync), k64 subchunk pipeline, 3 CTAs/SM.
// Grid = 512 CTAs: bid & 63 = n-group (128 W rows), bid >> 6 = k-group.
// Warp layout 2(m) x 4(n): warp owns 32 batch rows x 32 output cols.
// Phase shift (R9 scheme): iteration sub stages subchunk sub+1 before MMA(sub).
// ---------------------------------------------------------------------------
__global__ __launch_bounds__(NTHREADS, 3)
void dq_gemm_kernel(const int*   __restrict__ packed,
                    const float* __restrict__ scales,
                    float*       __restrict__ out)
{
    extern __shared__ __align__(16) char dsm[];
    const uint32_t sb = (uint32_t)__cvta_generic_to_shared(dsm);
    float* sScale = reinterpret_cast<float*>(dsm + SCALE_OFF);

    const int tid  = threadIdx.x;
    const int wid  = tid >> 5;
    const int lane = tid & 31;
    const int mh   = wid & 1;          // batch half
    const int ng   = wid >> 1;         // 32-col group
    const int n0   = (blockIdx.x & 63) * TILE_N;
    const int kg   = blockIdx.x >> 6;  // 0..7
    const int ks0  = kg * NSUB;        // global k64-subchunk base

    float acc[2][4][4];
    #pragma unroll
    for (int m = 0; m < 2; m++)
        #pragma unroll
        for (int n = 0; n < 4; n++)
            #pragma unroll
            for (int j = 0; j < 4; j++) acc[m][n][j] = 0.f;

    const uint4* pk4 = reinterpret_cast<const uint4*>(packed); // row stride 1024
    const uint32_t c1032b = 0x64086408u;                       // half2(1032,1032)
    const __half2 c1032 = *reinterpret_cast<const __half2*>(&c1032b);

    // ---- stage the scale table once: [NCH][TILE_N] ------------------------
    #pragma unroll
    for (int i = 0; i < (NCH * TILE_N) / NTHREADS; i++) {
        int idx = tid + i * NTHREADS;                // 0..1023
        int ch = idx >> 7, row = idx & 127;
        sScale[idx] = scales[(size_t)(n0 + row) * 64 + kg * NCH + ch];
    }

    // ---- packed-W register prefetch (one k64 sub = 1024 uint4 = 4/thread) -
    uint4 pv[4];
    auto prefetch = [&](int ks) {
        #pragma unroll
        for (int j = 0; j < 4; j++) {
            int u = tid + (j << 8);                  // 0..1023
            int row = u >> 3, kv = u & 7;
            pv[j] = pk4[(size_t)(n0 + row) * 1024 + ks * 8 + kv];
        }
    };

    // ---- x tile cp.async (512 x 16B units = 2/thread) ---------------------
    auto stage_x = [&](int ks, int s) {
        const uint32_t xb = sb + s * STAGE_BYTES + X_OFF;
        #pragma unroll
        for (int j = 0; j < 2; j++) {
            int u = tid + (j << 8);                  // 0..511
            int b = u >> 3, kv = u & 7;
            cp_async16(xb + b * RS + kv * 16,
                       &g_xh[(size_t)b * IN_K + ks * 64 + kv * 8]);
        }
        cp_commit();
    };

    // dequant pv (subchunk sub) -> W buffer s (4 x STS.128 / thread)
    auto dequant_sts = [&](int s, int sub) {
        const uint32_t stage = sb + s * STAGE_BYTES;
        const int lch = sub >> 1;                    // k128 scale chunk
        #pragma unroll
        for (int j = 0; j < 4; j++) {
            int u = tid + (j << 8);
            int row = u >> 3, kv = u & 7;
            __half2 s2 = __float2half2_rn(sScale[(lch << 7) + row]);
            uint32_t w[4] = { pv[j].x, pv[j].y, pv[j].z, pv[j].w };
            uint32_t o[4];
            #pragma unroll
            for (int q = 0; q < 4; q++) {
                uint32_t t = ((w[q] * 0x1001u) & 0x000F000Fu) | 0x64006400u;
                __half2 hv = __hmul2(__hsub2(*reinterpret_cast<__half2*>(&t), c1032), s2);
                o[q] = *reinterpret_cast<uint32_t*>(&hv);
            }
            asm volatile("st.shared.v4.b32 [%0], {%1,%2,%3,%4};"
                         :: "r"(stage + row * RS + kv * 16),
                            "r"(o[0]), "r"(o[1]), "r"(o[2]), "r"(o[3]) : "memory");
        }
    };

    // ---- prologue ---------------------------------------------------------
    prefetch(ks0);           // pv = packed[sub 0]
    stage_x(ks0, 0);         // x[0] in flight
    __syncthreads();         // sScale visible to all
    dequant_sts(0, 0);       // W[0] STS -> stage 0
    prefetch(ks0 + 1);       // pv = packed[sub 1]

    // Invariant at iteration entry (sub, s = sub&1):
    //   x[sub] cp.async group pending; W[sub] STS issued into stage s;
    //   pv = packed[sub+1].
    for (int sub = 0; sub < NSUB; sub++) {
        const int s = sub & 1;

        asm volatile("cp.async.wait_group 0;" ::: "memory");  // x[sub] landed
        __syncthreads();     // W[sub]/x[sub] visible; stage s^1 free

        if (sub + 1 < NSUB) {
            stage_x(ks0 + sub + 1, s ^ 1);       // x[sub+1] in flight
            dequant_sts(s ^ 1, sub + 1);         // W[sub+1] STS (other buffer)
            if (sub + 2 < NSUB) prefetch(ks0 + sub + 2);  // LDGs overlap MMA
        }

        // ---- MMA(sub): 4 k16 tiles, warp tile 32(m) x 32(n), stage s ------
        const uint32_t wbase = sb + s * STAGE_BYTES;
        const uint32_t xbase = wbase + X_OFF;
        #pragma unroll
        for (int kt = 0; kt < 4; kt++) {
            uint32_t b[4][2];             // [nt][b0,b1]
            #pragma unroll
            for (int np = 0; np < 2; np++) {
                int br = ng * 32 + np * 16 + ((lane >> 4) & 1) * 8 + (lane & 7);
                int bc = kt * 16 + ((lane >> 3) & 1) * 8;
                ldsm_x4(b[np*2][0], b[np*2][1], b[np*2+1][0], b[np*2+1][1],
                        wbase + (uint32_t)(br * RS + bc * 2));
            }
            #pragma unroll
            for (int mt = 0; mt < 2; mt++) {
                uint32_t a0, a1, a2, a3;
                int ar = mh * 32 + mt * 16 + (lane & 15);
                int ac = kt * 16 + (lane >> 4) * 8;
                ldsm_x4(a0, a1, a2, a3, xbase + (uint32_t)(ar * RS + ac * 2));
                #pragma unroll
                for (int nt = 0; nt < 4; nt++)
                    mma_16816(acc[mt][nt], a0, a1, a2, a3, b[nt][0], b[nt][1]);
            }
        }
    }

    // ---- epilogue: vectorized float2 atomics (k-split merge) --------------
    #pragma unroll
    for (int mt = 0; mt < 2; mt++) {
        #pragma unroll
        for (int nt = 0; nt < 4; nt++) {
            int m = mh * 32 + mt * 16 + (lane >> 2);
            int n = n0 + ng * 32 + nt * 8 + (lane & 3) * 2;
            atomicAdd(reinterpret_cast<float2*>(&out[(size_t)m * OUT_N + n]),
                      make_float2(acc[mt][nt][0], acc[mt][nt][1]));
            atomicAdd(reinterpret_cast<float2*>(&out[(size_t)(m + 8) * OUT_N + n]),
                      make_float2(acc[mt][nt][2], acc[mt][nt][3]));
        }
    }
}

// ---------------------------------------------------------------------------
extern "C" void kernel_launch(void* const* d_in, const int* in_sizes, int n_in,
                              void* d_out, int out_size) {
    const float* x      = (const float*)d_in[0];
    const int*   packed = (const int*)d_in[1];
    const float* scales = (const float*)d_in[2];
    float*       out    = (float*)d_out;

    cudaFuncSetAttribute(dq_gemm_kernel,
                         cudaFuncAttributeMaxDynamicSharedMemorySize, SMEM_TOTAL);

    prep_kernel<<<512, 256>>>(x, out);
    dq_gemm_kernel<<<NGRPS * KSPLIT, NTHREADS, SMEM_TOTAL>>>(packed, scales, out);
}